// round 2
// baseline (speedup 1.0000x reference)
#include <cuda_runtime.h>
#include <cuda_fp16.h>
#include <cstdint>

#define DINLINE __device__ __forceinline__

// ---------------- problem constants ----------------
constexpr int NB = 16, CINC = 512, COUTC = 512;
constexpr int HWP = 64 * 64;           // 4096
constexpr int M_TOTAL = NB * HWP;      // 65536
constexpr int KTAPS = 9;

// GEMM tiling (mma.sync path; sm_100 baseline has NO tcgen05)
constexpr int TM = 128;                // spatial rows per tile (2 image rows)
constexpr int TN = 128;                // cout per tile
constexpr int KC = 32;                 // ci per chunk
constexpr int NCHUNKS = KTAPS * (CINC / KC);   // 144
constexpr int CTHREADS = 256;
constexpr int STAGES = 4;

// SMEM: per stage, A tile 128 rows x 32 fp16 (64B) padded to 80B rows (bank-conflict-free),
// B tile same shape. 4 stages each.
constexpr int ROWB = 80;
constexpr int STAGE_BYTES = 128 * ROWB;            // 10240
constexpr int OFF_B = STAGES * STAGE_BYTES;        // 40960
constexpr int SMEM_TOTAL = 2 * STAGES * STAGE_BYTES; // 81920

constexpr float WSCALE    = 0.014731391274719738f;   // 1/sqrt(9*512)
constexpr float WSCALE2   = 1.0f / 4608.0f;
constexpr float INV_SQRTW = 0.044194173824159216f;   // 1/sqrt(512)
constexpr float LRELU_G   = 1.4142135623730951f;

// ---------------- scratch (device globals: allocation-free) ----------------
__device__ __align__(128) __half g_xmod[(size_t)M_TOTAL * CINC];      // x * s in fp16
__device__ __align__(128) __half g_whT[(size_t)KTAPS * COUTC * CINC]; // [tap][co][ci] * wscale
__device__ __align__(128) float  g_s[NB * CINC];
__device__ __align__(128) float  g_wsq[CINC * COUTC];
__device__ __align__(128) float  g_d[NB * COUTC];

// ---------------- PTX helpers ----------------
DINLINE uint32_t smem_u32(const void* p) {
    uint32_t a;
    asm("{ .reg .u64 t; cvta.to.shared.u64 t, %1; cvt.u32.u64 %0, t; }" : "=r"(a) : "l"(p));
    return a;
}
DINLINE void cp16(uint32_t dst, const void* src, uint32_t sz) {
    asm volatile("cp.async.cg.shared.global [%0], [%1], 16, %2;"
                 :: "r"(dst), "l"(src), "r"(sz) : "memory");
}
DINLINE void cp_commit() { asm volatile("cp.async.commit_group;" ::: "memory"); }
DINLINE void cp_wait3()  { asm volatile("cp.async.wait_group 3;" ::: "memory"); }

#define LDSM4(r, addr)                                                          \
    asm volatile("ldmatrix.sync.aligned.m8n8.x4.shared.b16 {%0,%1,%2,%3}, [%4];" \
                 : "=r"((r)[0]), "=r"((r)[1]), "=r"((r)[2]), "=r"((r)[3])        \
                 : "r"(addr))

#define MMA16816(d, a, b0, b1)                                                  \
    asm volatile("mma.sync.aligned.m16n8k16.row.col.f32.f16.f16.f32 "           \
                 "{%0,%1,%2,%3}, {%4,%5,%6,%7}, {%8,%9}, {%0,%1,%2,%3};"        \
                 : "+f"((d)[0]), "+f"((d)[1]), "+f"((d)[2]), "+f"((d)[3])        \
                 : "r"((a)[0]), "r"((a)[1]), "r"((a)[2]), "r"((a)[3]),           \
                   "r"(b0), "r"(b1))

// ---------------- prep kernels ----------------
// s[n][c] = dlatents[n, 8] @ (affine_w / sqrt(512)) + affine_b
__global__ void k_affine(const float* __restrict__ dl, const float* __restrict__ aw,
                         const float* __restrict__ ab) {
    int n = blockIdx.x, c = threadIdx.x;  // 16 blocks x 512 threads
    const float* row = dl + ((size_t)n * 18 + 8) * 512;
    float acc = 0.f;
    #pragma unroll 4
    for (int w = 0; w < 512; w++) acc += row[w] * __ldg(aw + (size_t)w * 512 + c);
    g_s[n * 512 + c] = acc * INV_SQRTW + ab[c];
}

// wsq[ci][co] = sum_taps conv_w^2
__global__ void k_wsq(const float* __restrict__ cw) {
    int idx = blockIdx.x * blockDim.x + threadIdx.x;  // 262144
    float acc = 0.f;
    #pragma unroll
    for (int t = 0; t < 9; t++) { float v = __ldg(cw + (size_t)t * 262144 + idx); acc += v * v; }
    g_wsq[idx] = acc;
}

// d[n][co] = rsqrt(wscale^2 * sum_ci s^2 * wsq + 1e-8)
__global__ void k_demod() {
    __shared__ float s2[512];
    int n = blockIdx.x;
    int co = blockIdx.y * 128 + threadIdx.x;
    for (int i = threadIdx.x; i < 512; i += 128) { float v = g_s[n * 512 + i]; s2[i] = v * v; }
    __syncthreads();
    float acc = 0.f;
    #pragma unroll 4
    for (int ci = 0; ci < 512; ci++) acc += s2[ci] * g_wsq[ci * 512 + co];
    g_d[n * 512 + co] = rsqrtf(acc * WSCALE2 + 1e-8f);
}

// xmod = fp16(x * s)
__global__ void k_xmod(const float* __restrict__ x) {
    int g = blockIdx.x * blockDim.x + threadIdx.x;  // 4,194,304 groups of 8
    int ci8 = (g & 63) << 3;
    int m = g >> 6;
    int n = m >> 12;
    const float4* xp = (const float4*)(x + (size_t)m * 512 + ci8);
    const float4* sp = (const float4*)(g_s + n * 512 + ci8);
    float4 x0 = __ldg(xp), x1 = __ldg(xp + 1);
    float4 s0 = sp[0], s1 = sp[1];
    __half2 h0 = __floats2half2_rn(x0.x * s0.x, x0.y * s0.y);
    __half2 h1 = __floats2half2_rn(x0.z * s0.z, x0.w * s0.w);
    __half2 h2 = __floats2half2_rn(x1.x * s1.x, x1.y * s1.y);
    __half2 h3 = __floats2half2_rn(x1.z * s1.z, x1.w * s1.w);
    uint4 out;
    out.x = *(uint32_t*)&h0; out.y = *(uint32_t*)&h1;
    out.z = *(uint32_t*)&h2; out.w = *(uint32_t*)&h3;
    *(uint4*)(g_xmod + (size_t)m * 512 + ci8) = out;
}

// whT[tap][co][ci] = fp16(conv_w[tap][ci][co] * wscale)  (SMEM-tiled transpose)
__global__ void k_whT(const float* __restrict__ cw) {
    __shared__ float tile[32][33];
    int co0 = blockIdx.x * 32, ci0 = blockIdx.y * 32, tap = blockIdx.z;
    int tx = threadIdx.x, ty = threadIdx.y;  // (32, 8)
    #pragma unroll
    for (int r = 0; r < 4; r++) {
        int ci = ty + r * 8;
        tile[ci][tx] = __ldg(cw + ((size_t)tap * 512 + ci0 + ci) * 512 + co0 + tx);
    }
    __syncthreads();
    #pragma unroll
    for (int r = 0; r < 4; r++) {
        int co = ty + r * 8;
        g_whT[((size_t)tap * 512 + co0 + co) * 512 + ci0 + tx] =
            __float2half_rn(tile[tx][co] * WSCALE);
    }
}

// ---------------- chunk loader (cp.async) ----------------
DINLINE void load_chunk(uint32_t sb, int c, int tid, int img, int h0, int n0) {
    int buf = c & (STAGES - 1);
    int tap = c >> 4;                 // 16 ci-chunks per tap
    int ci0 = (c & 15) << 5;
    int dh = tap / 3 - 1, dw = tap % 3 - 1;
    uint32_t adst = sb + buf * STAGE_BYTES;
    uint32_t bdst = sb + OFF_B + buf * STAGE_BYTES;
    #pragma unroll
    for (int i = 0; i < 2; i++) {
        int idx = tid + i * 256;
        int row = idx >> 2, ch = idx & 3;
        int hh = h0 + (row >> 6) + dh;
        int ww = (row & 63) + dw;
        bool ok = ((unsigned)hh < 64u) && ((unsigned)ww < 64u);
        const __half* src = g_xmod +
            ((size_t)((img * 64 + (ok ? hh : 0)) * 64 + (ok ? ww : 0)) * 512 + ci0 + ch * 8);
        cp16(adst + row * ROWB + ch * 16, src, ok ? 16u : 0u);
    }
    #pragma unroll
    for (int i = 0; i < 2; i++) {
        int idx = tid + i * 256;
        int row = idx >> 2, ch = idx & 3;
        const __half* src = g_whT + ((size_t)(tap * 512 + n0 + row) * 512 + ci0 + ch * 8);
        cp16(bdst + row * ROWB + ch * 16, src, 16u);
    }
}

// ---------------- main conv kernel (implicit GEMM, mma.sync f16) ----------------
__global__ void __launch_bounds__(CTHREADS) k_conv(
    const float* __restrict__ conv_b, const float* __restrict__ noise,
    const float* __restrict__ nstr, float* __restrict__ out)
{
    extern __shared__ char smem[];
    uint32_t sb = smem_u32(smem);
    int tid = threadIdx.x, wid = tid >> 5, lane = tid & 31;

    int bid = blockIdx.x;             // 2048 blocks: 512 M-tiles x 4 N-tiles
    int nt = bid & 3, mt = bid >> 2;
    int m0 = mt * TM;
    int n0 = nt * TN;
    int img = m0 >> 12;               // batch index
    int h0 = (m0 >> 6) & 63;          // first image row of this tile

    int wm = wid & 1, wn = wid >> 1;  // warp grid 2(M) x 4(N); warp tile 64x32

    float acc[4][4][4];
    #pragma unroll
    for (int i = 0; i < 4; i++)
        #pragma unroll
        for (int j = 0; j < 4; j++)
            #pragma unroll
            for (int q = 0; q < 4; q++) acc[i][j][q] = 0.f;

    // prologue: fill STAGES-1 stages
    #pragma unroll
    for (int s = 0; s < STAGES - 1; s++) { load_chunk(sb, s, tid, img, h0, n0); cp_commit(); }

    // per-lane ldmatrix base offsets
    // A x4: lanes 0-7 rows m0-7, 8-15 rows m8-15, 16-23 rows m0-7 (+16B), 24-31 rows m8-15 (+16B)
    uint32_t a_off = (uint32_t)((wm * 64 + (lane & 7) + ((lane >> 3) & 1) * 8) * ROWB
                                + (lane >> 4) * 16);
    // B x4: lanes 0-7 rows n0-7, 8-15 rows n0-7 (+16B), 16-23 rows n8-15, 24-31 rows n8-15 (+16B)
    uint32_t b_off = (uint32_t)((wn * 32 + (lane & 7) + ((lane >> 4) & 1) * 8) * ROWB
                                + ((lane >> 3) & 1) * 16);

    for (int c = 0; c < NCHUNKS; c++) {
        int pre = c + STAGES - 1;
        if (pre < NCHUNKS) load_chunk(sb, pre, tid, img, h0, n0);
        cp_commit();
        cp_wait3();
        __syncthreads();

        uint32_t abase = sb + (c & (STAGES - 1)) * STAGE_BYTES + a_off;
        uint32_t bbase = sb + OFF_B + (c & (STAGES - 1)) * STAGE_BYTES + b_off;

        #pragma unroll
        for (int kh = 0; kh < 2; kh++) {
            uint32_t a[4][4], b[2][4];
            #pragma unroll
            for (int mf = 0; mf < 4; mf++) LDSM4(a[mf], abase + mf * 16 * ROWB + kh * 32);
            #pragma unroll
            for (int p = 0; p < 2; p++)    LDSM4(b[p], bbase + p * 16 * ROWB + kh * 32);
            #pragma unroll
            for (int mf = 0; mf < 4; mf++)
                #pragma unroll
                for (int nf = 0; nf < 4; nf++)
                    MMA16816(acc[mf][nf], a[mf], b[nf >> 1][(nf & 1) * 2], b[nf >> 1][(nf & 1) * 2 + 1]);
        }
        __syncthreads();
    }

    // ---------------- fused epilogue ----------------
    float ns = __ldg(nstr);
    int base_m = m0 + wm * 64;
    int base_n = n0 + wn * 32;
    int r0 = lane >> 2;
    int cpair = (lane & 3) * 2;

    #pragma unroll
    for (int mf = 0; mf < 4; mf++) {
        int mA = base_m + mf * 16 + r0;
        int mB = mA + 8;
        float nzA = __ldg(noise + mA) * ns;
        float nzB = __ldg(noise + mB) * ns;
        #pragma unroll
        for (int nf = 0; nf < 4; nf++) {
            int co = base_n + nf * 8 + cpair;
            float2 dd = *(const float2*)(g_d + img * 512 + co);
            float2 bb = *(const float2*)(conv_b + co);
            float v0 = acc[mf][nf][0] * dd.x + nzA + bb.x;
            float v1 = acc[mf][nf][1] * dd.y + nzA + bb.y;
            float v2 = acc[mf][nf][2] * dd.x + nzB + bb.x;
            float v3 = acc[mf][nf][3] * dd.y + nzB + bb.y;
            v0 = (v0 > 0.f ? v0 : 0.2f * v0) * LRELU_G;
            v1 = (v1 > 0.f ? v1 : 0.2f * v1) * LRELU_G;
            v2 = (v2 > 0.f ? v2 : 0.2f * v2) * LRELU_G;
            v3 = (v3 > 0.f ? v3 : 0.2f * v3) * LRELU_G;
            float2 oA = make_float2(fminf(fmaxf(v0, -256.f), 256.f),
                                    fminf(fmaxf(v1, -256.f), 256.f));
            float2 oB = make_float2(fminf(fmaxf(v2, -256.f), 256.f),
                                    fminf(fmaxf(v3, -256.f), 256.f));
            *(float2*)(out + (size_t)mA * 512 + co) = oA;
            *(float2*)(out + (size_t)mB * 512 + co) = oB;
        }
    }
}

// ---------------- launcher ----------------
// input order: x, dlatents, affine_w, affine_b, conv_w, conv_b, noise, noise_strength
extern "C" void kernel_launch(void* const* d_in, const int* in_sizes, int n_in,
                              void* d_out, int out_size) {
    const float* x   = (const float*)d_in[0];
    const float* dl  = (const float*)d_in[1];
    const float* aw  = (const float*)d_in[2];
    const float* ab  = (const float*)d_in[3];
    const float* cw  = (const float*)d_in[4];
    const float* cb  = (const float*)d_in[5];
    const float* noi = (const float*)d_in[6];
    const float* nst = (const float*)d_in[7];
    float* out = (float*)d_out;

    cudaFuncSetAttribute(k_conv, cudaFuncAttributeMaxDynamicSharedMemorySize, SMEM_TOTAL);

    k_affine<<<NB, 512>>>(dl, aw, ab);
    k_wsq<<<1024, 256>>>(cw);
    k_demod<<<dim3(NB, 4), 128>>>();
    k_xmod<<<16384, 256>>>(x);
    k_whT<<<dim3(16, 16, 9), dim3(32, 8)>>>(cw);
    k_conv<<<(M_TOTAL / TM) * (COUTC / TN), CTHREADS, SMEM_TOTAL>>>(cb, noi, nst, out);
}

// round 3
// speedup vs baseline: 1.3296x; 1.3296x over previous
#include <cuda_runtime.h>
#include <cuda_fp16.h>
#include <cstdint>

#define DINLINE __device__ __forceinline__

// ---------------- problem constants ----------------
constexpr int NB = 16, CINC = 512, COUTC = 512;
constexpr int HWP = 64 * 64;            // 4096
constexpr int M_TOTAL = NB * HWP;       // 65536
constexpr int KTAPS = 9;

// GEMM tiling
constexpr int TM = 128;                 // pixels per tile (2 image rows)
constexpr int TN = 128;                 // cout per tile
constexpr int KC = 64;                  // ci per chunk (one 128B row)
constexpr int NCHUNKS = KTAPS * (CINC / KC);   // 72
constexpr int CTHREADS = 256;
constexpr int STAGES = 3;

// xpk plane: 128 guard rows + 65536 + 128 guard rows
constexpr int PLANE = 128 + M_TOTAL + 128;     // 65792

// SMEM: per stage A 128x128B (16KB) + B 128x128B (16KB)
constexpr int STB = 32768;
constexpr int OFF_MBAR = STAGES * STB;         // 98304
constexpr int SMEM_TOTAL = OFF_MBAR + 128;     // 98432

constexpr float WSCALE    = 0.014731391274719738f;   // 1/sqrt(9*512)
constexpr float WSCALE2   = 1.0f / 4608.0f;
constexpr float INV_SQRTW = 0.044194173824159216f;   // 1/sqrt(512)
constexpr float LRELU_G   = 1.4142135623730951f;

// ---------------- scratch (device globals: allocation-free) ----------------
__device__ __align__(128) __half g_xpk[(size_t)8 * PLANE * 64];        // [cc][row][64ci] swizzled
__device__ __align__(128) __half g_wpk[(size_t)KTAPS * 8 * COUTC * 64];// [tap][cc][co][64ci] swizzled
__device__ __align__(128) float  g_s[NB * CINC];
__device__ __align__(128) float  g_wsq[CINC * COUTC];
__device__ __align__(128) float  g_d[NB * COUTC];

// ---------------- PTX helpers ----------------
DINLINE uint32_t smem_u32(const void* p) {
    uint32_t a;
    asm("{ .reg .u64 t; cvta.to.shared.u64 t, %1; cvt.u32.u64 %0, t; }" : "=r"(a) : "l"(p));
    return a;
}
DINLINE void mbar_init(uint32_t mbar, uint32_t cnt) {
    asm volatile("mbarrier.init.shared.b64 [%0], %1;" :: "r"(mbar), "r"(cnt) : "memory");
}
DINLINE void mbar_expect_tx(uint32_t mbar, uint32_t tx) {
    asm volatile("mbarrier.arrive.expect_tx.shared.b64 _, [%0], %1;" :: "r"(mbar), "r"(tx) : "memory");
}
DINLINE void mbar_wait(uint32_t mbar, uint32_t parity) {
    asm volatile(
        "{\n\t.reg .pred P;\n\t"
        "WL_%=:\n\t"
        "mbarrier.try_wait.parity.acquire.cta.shared::cta.b64 P, [%0], %1, 0x989680;\n\t"
        "@P bra.uni WD_%=;\n\t"
        "bra.uni WL_%=;\n\t"
        "WD_%=:\n\t}"
        :: "r"(mbar), "r"(parity) : "memory");
}
DINLINE void bulk_g2s(uint32_t dst, const void* src, uint32_t bytes, uint32_t mbar) {
    asm volatile("cp.async.bulk.shared::cluster.global.mbarrier::complete_tx::bytes "
                 "[%0], [%1], %2, [%3];"
                 :: "r"(dst), "l"(src), "r"(bytes), "r"(mbar) : "memory");
}
DINLINE void fence_async_shared() {
    asm volatile("fence.proxy.async.shared::cta;" ::: "memory");
}

#define LDSM4(r, addr)                                                          \
    asm volatile("ldmatrix.sync.aligned.m8n8.x4.shared.b16 {%0,%1,%2,%3}, [%4];" \
                 : "=r"((r)[0]), "=r"((r)[1]), "=r"((r)[2]), "=r"((r)[3])        \
                 : "r"(addr))

#define MMA16816(d, a, b0, b1)                                                  \
    asm volatile("mma.sync.aligned.m16n8k16.row.col.f32.f16.f16.f32 "           \
                 "{%0,%1,%2,%3}, {%4,%5,%6,%7}, {%8,%9}, {%0,%1,%2,%3};"        \
                 : "+f"((d)[0]), "+f"((d)[1]), "+f"((d)[2]), "+f"((d)[3])        \
                 : "r"((a)[0]), "r"((a)[1]), "r"((a)[2]), "r"((a)[3]),           \
                   "r"(b0), "r"(b1))

// ---------------- prep kernels ----------------
__global__ void k_affine(const float* __restrict__ dl, const float* __restrict__ aw,
                         const float* __restrict__ ab) {
    int n = blockIdx.x, c = threadIdx.x;  // 16 x 512
    const float* row = dl + ((size_t)n * 18 + 8) * 512;
    float acc = 0.f;
    #pragma unroll 4
    for (int w = 0; w < 512; w++) acc += row[w] * __ldg(aw + (size_t)w * 512 + c);
    g_s[n * 512 + c] = acc * INV_SQRTW + ab[c];
}

__global__ void k_wsq(const float* __restrict__ cw) {
    int idx = blockIdx.x * blockDim.x + threadIdx.x;  // 262144
    float acc = 0.f;
    #pragma unroll
    for (int t = 0; t < 9; t++) { float v = __ldg(cw + (size_t)t * 262144 + idx); acc += v * v; }
    g_wsq[idx] = acc;
}

__global__ void k_demod() {
    __shared__ float s2[512];
    int n = blockIdx.x;
    int co = blockIdx.y * 128 + threadIdx.x;
    for (int i = threadIdx.x; i < 512; i += 128) { float v = g_s[n * 512 + i]; s2[i] = v * v; }
    __syncthreads();
    float acc = 0.f;
    #pragma unroll 4
    for (int ci = 0; ci < 512; ci++) acc += s2[ci] * g_wsq[ci * 512 + co];
    g_d[n * 512 + co] = rsqrtf(acc * WSCALE2 + 1e-8f);
}

// xpk[cc][128 + m][word j at j^(m&7)] = fp16(x[m][cc*64 + 8j..8j+7] * s)
__global__ void k_xpk(const float* __restrict__ x) {
    int g = blockIdx.x * blockDim.x + threadIdx.x;  // 524288 threads
    int cc = g & 7, m = g >> 3;
    int n = m >> 12;
    const float4* xp = (const float4*)(x + (size_t)m * 512 + cc * 64);
    const float4* sp = (const float4*)(g_s + n * 512 + cc * 64);
    __half* dst = g_xpk + ((size_t)cc * PLANE + 128 + m) * 64;
    int pm = m & 7;
    #pragma unroll
    for (int w = 0; w < 8; w++) {
        float4 x0 = __ldg(xp + 2 * w), x1 = __ldg(xp + 2 * w + 1);
        float4 s0 = sp[2 * w], s1 = sp[2 * w + 1];
        __half2 h0 = __floats2half2_rn(x0.x * s0.x, x0.y * s0.y);
        __half2 h1 = __floats2half2_rn(x0.z * s0.z, x0.w * s0.w);
        __half2 h2 = __floats2half2_rn(x1.x * s1.x, x1.y * s1.y);
        __half2 h3 = __floats2half2_rn(x1.z * s1.z, x1.w * s1.w);
        uint4 o;
        o.x = *(uint32_t*)&h0; o.y = *(uint32_t*)&h1;
        o.z = *(uint32_t*)&h2; o.w = *(uint32_t*)&h3;
        *(uint4*)(dst + (size_t)((w ^ pm) * 8)) = o;
    }
}

// wpk[tap][cc][co][word j at j^(co&7)] = fp16(conv_w[tap][ci][co] * wscale), transposed
__global__ void k_wpk(const float* __restrict__ cw) {
    __shared__ float tile[64][33];
    int co0 = blockIdx.x * 32, cc = blockIdx.y, tap = blockIdx.z;
    int ci0 = cc * 64;
    int tx = threadIdx.x, ty = threadIdx.y;  // (32, 8)
    #pragma unroll
    for (int r = 0; r < 8; r++) {
        int ci = ty * 8 + r;
        tile[ci][tx] = __ldg(cw + ((size_t)tap * 512 + ci0 + ci) * 512 + co0 + tx);
    }
    __syncthreads();
    int co = co0 + tx, w = ty;
    __half h[8];
    #pragma unroll
    for (int q = 0; q < 8; q++) h[q] = __float2half_rn(tile[w * 8 + q][tx] * WSCALE);
    __half* dst = g_wpk + ((size_t)((tap * 8 + cc) * 512) + co) * 64 + (w ^ (co & 7)) * 8;
    *(uint4*)dst = *(uint4*)h;
}

// ---------------- chunk issue (bulk copies) ----------------
DINLINE void issue_chunk(uint32_t sb, uint32_t mb, int c, int stage, int m0, int n0) {
    int tap = c >> 3, cc = c & 7;
    int dh = tap / 3 - 1, dw = tap % 3 - 1;
    const __half* srcA = g_xpk + ((size_t)cc * PLANE + 128 + m0 + dh * 64 + dw) * 64;
    const __half* srcB = g_wpk + ((size_t)((tap * 8 + cc) * 512) + n0) * 64;
    uint32_t mbar = mb + stage * 8;
    mbar_expect_tx(mbar, 32768u);
    bulk_g2s(sb + stage * STB,         srcA, 16384u, mbar);
    bulk_g2s(sb + stage * STB + 16384, srcB, 16384u, mbar);
}

// ---------------- main conv kernel ----------------
__global__ void __launch_bounds__(CTHREADS, 2) k_conv(
    const float* __restrict__ conv_b, const float* __restrict__ noise,
    const float* __restrict__ nstr, float* __restrict__ out)
{
    extern __shared__ char smem[];
    uint32_t sb = smem_u32(smem);
    int tid = threadIdx.x, wid = tid >> 5, lane = tid & 31;

    int bid = blockIdx.x;             // 2048 blocks: 512 M-tiles x 4 N-tiles
    int nt = bid & 3, mt = bid >> 2;
    int m0 = mt * TM, n0 = nt * TN;
    int img = m0 >> 12;
    int h0 = (m0 >> 6) & 63;          // tile covers image rows h0, h0+1

    int wm = wid & 1, wn = wid >> 1;  // warp grid 2(M) x 4(N); warp tile 64x32
    uint32_t mb = sb + OFF_MBAR;

    if (tid == 0) {
        mbar_init(mb, 1); mbar_init(mb + 8, 1); mbar_init(mb + 16, 1);
    }
    __syncthreads();

    if (tid == 0) { issue_chunk(sb, mb, 0, 0, m0, n0); issue_chunk(sb, mb, 1, 1, m0, n0); }

    float acc[4][4][4];
    #pragma unroll
    for (int i = 0; i < 4; i++)
        #pragma unroll
        for (int j = 0; j < 4; j++)
            #pragma unroll
            for (int q = 0; q < 4; q++) acc[i][j][q] = 0.f;

    int rbase = (lane & 7) + ((lane >> 3) & 1) * 8 + wm * 64;
    int ahi   = lane >> 4;
    int bsel  = (lane >> 3) & 1;
    int rB    = wn * 32 + (lane & 7) + ((lane >> 4) & 1) * 8;
    int permB = lane & 7;

    int stage = 0, par = 0;
    for (int c = 0; c < NCHUNKS; c++) {
        mbar_wait(mb + stage * 8, par);

        int tap = c >> 3;
        int dh = tap / 3 - 1, dw = tap % 3 - 1;
        char* ab = smem + stage * STB;

        bool st = false;
        if (dw != 0 && tid < 16) {
            int row = ((dw < 0) ? 0 : 63) + (tid >> 3) * 64;
            ((uint4*)(ab + row * 128))[tid & 7] = make_uint4(0, 0, 0, 0);
            st = true;
        }
        if (h0 + dh < 0) {          // rows 0..63 invalid (bytes 0..8191)
            ((uint4*)ab)[tid] = make_uint4(0, 0, 0, 0);
            ((uint4*)ab)[tid + 256] = make_uint4(0, 0, 0, 0);
            st = true;
        }
        if (h0 + 1 + dh > 63) {     // rows 64..127 invalid (bytes 8192..16383)
            ((uint4*)(ab + 8192))[tid] = make_uint4(0, 0, 0, 0);
            ((uint4*)(ab + 8192))[tid + 256] = make_uint4(0, 0, 0, 0);
            st = true;
        }
        if (st) fence_async_shared();
        __syncthreads();

        if (tid == 0 && c + 2 < NCHUNKS) {
            int s2 = stage + 2; if (s2 >= STAGES) s2 -= STAGES;
            issue_chunk(sb, mb, c + 2, s2, m0, n0);
        }

        uint32_t Ab = sb + stage * STB;
        uint32_t Bb = Ab + 16384;

        #pragma unroll
        for (int kh = 0; kh < 4; kh++) {
            uint32_t a[4][4], b[2][4];
            #pragma unroll
            for (int mf = 0; mf < 4; mf++) {
                int rA = rbase + mf * 16;
                uint32_t ad = Ab + rA * 128 + (((2 * kh + ahi) ^ ((rA + dw) & 7)) * 16);
                LDSM4(a[mf], ad);
            }
            #pragma unroll
            for (int p = 0; p < 2; p++) {
                int r = rB + p * 16;
                uint32_t bd = Bb + r * 128 + (((2 * kh + bsel) ^ permB) * 16);
                LDSM4(b[p], bd);
            }
            #pragma unroll
            for (int mf = 0; mf < 4; mf++)
                #pragma unroll
                for (int nf = 0; nf < 4; nf++)
                    MMA16816(acc[mf][nf], a[mf], b[nf >> 1][(nf & 1) * 2],
                             b[nf >> 1][(nf & 1) * 2 + 1]);
        }

        if (++stage == STAGES) { stage = 0; par ^= 1; }
    }

    // ---------------- fused epilogue ----------------
    float ns = __ldg(nstr);
    int base_m = m0 + wm * 64;
    int base_n = n0 + wn * 32;
    int r0 = lane >> 2;
    int cpair = (lane & 3) * 2;

    #pragma unroll
    for (int mf = 0; mf < 4; mf++) {
        int mA = base_m + mf * 16 + r0;
        int mB = mA + 8;
        float nzA = __ldg(noise + mA) * ns;
        float nzB = __ldg(noise + mB) * ns;
        #pragma unroll
        for (int nf = 0; nf < 4; nf++) {
            int co = base_n + nf * 8 + cpair;
            float2 dd = *(const float2*)(g_d + img * 512 + co);
            float2 bb = *(const float2*)(conv_b + co);
            float v0 = acc[mf][nf][0] * dd.x + nzA + bb.x;
            float v1 = acc[mf][nf][1] * dd.y + nzA + bb.y;
            float v2 = acc[mf][nf][2] * dd.x + nzB + bb.x;
            float v3 = acc[mf][nf][3] * dd.y + nzB + bb.y;
            v0 = (v0 > 0.f ? v0 : 0.2f * v0) * LRELU_G;
            v1 = (v1 > 0.f ? v1 : 0.2f * v1) * LRELU_G;
            v2 = (v2 > 0.f ? v2 : 0.2f * v2) * LRELU_G;
            v3 = (v3 > 0.f ? v3 : 0.2f * v3) * LRELU_G;
            float2 oA = make_float2(fminf(fmaxf(v0, -256.f), 256.f),
                                    fminf(fmaxf(v1, -256.f), 256.f));
            float2 oB = make_float2(fminf(fmaxf(v2, -256.f), 256.f),
                                    fminf(fmaxf(v3, -256.f), 256.f));
            *(float2*)(out + (size_t)mA * 512 + co) = oA;
            *(float2*)(out + (size_t)mB * 512 + co) = oB;
        }
    }
}

// ---------------- launcher ----------------
// input order: x, dlatents, affine_w, affine_b, conv_w, conv_b, noise, noise_strength
extern "C" void kernel_launch(void* const* d_in, const int* in_sizes, int n_in,
                              void* d_out, int out_size) {
    const float* x   = (const float*)d_in[0];
    const float* dl  = (const float*)d_in[1];
    const float* aw  = (const float*)d_in[2];
    const float* ab  = (const float*)d_in[3];
    const float* cw  = (const float*)d_in[4];
    const float* cb  = (const float*)d_in[5];
    const float* noi = (const float*)d_in[6];
    const float* nst = (const float*)d_in[7];
    float* out = (float*)d_out;

    cudaFuncSetAttribute(k_conv, cudaFuncAttributeMaxDynamicSharedMemorySize, SMEM_TOTAL);

    k_affine<<<NB, 512>>>(dl, aw, ab);
    k_wsq<<<1024, 256>>>(cw);
    k_demod<<<dim3(NB, 4), 128>>>();
    k_xpk<<<2048, 256>>>(x);
    k_wpk<<<dim3(16, 8, 9), dim3(32, 8)>>>(cw);
    k_conv<<<(M_TOTAL / TM) * (COUTC / TN), CTHREADS, SMEM_TOTAL>>>(cb, noi, nst, out);
}